// round 16
// baseline (speedup 1.0000x reference)
#include <cuda_runtime.h>
#include <cuda_fp16.h>
#include <math.h>

#define B_ 256
#define V_ 128
#define M_ 256
#define H_ 1024
#define TD 10
#define IN_DIM 35840          // (V + TD + 1 + 1) * M
#define KC 8                  // split-K chunks
#define KPC (IN_DIM / KC)     // 4480
#define BM 128
#define BN 64                 // per weight matrix (dual-gemm per CTA)
#define BK 64
#define NITER (KPC / BK)      // 70
#define PAB 144               // A smem row pitch bytes (64 halves + 16B pad)
#define PWF 68                // B smem k-row pitch in floats (272 B)
#define A_STG 18432           // 128 * 144
#define B_MAT 17408           // 64 * 272
#define B_STG (2 * B_MAT)     // 34816
#define STG (A_STG + B_STG)   // 53248
#define SMEM_BYTES (2 * STG)  // 106496 -> 2 CTAs/SM (213 KB < 228 KB)
#define NB 4                  // b-rows batched per out_part block

// ---------------- device scratch (no allocations allowed) ----------------
__device__ __half g_predh[B_ * IN_DIM];     // fp16-rounded features
__device__ float g_h1p[KC][B_ * H_];        // split-K partials, GEMM 1
__device__ float g_hgp[KC][B_ * H_];        // split-K partials, gate GEMM
__device__ float g_opart[4][B_ * V_];       // out-gemm k-split partials

__device__ __forceinline__ void mma16(float c[4], const unsigned a[4],
                                      unsigned b0, unsigned b1) {
    asm volatile(
        "mma.sync.aligned.m16n8k16.row.col.f32.f16.f16.f32 "
        "{%0,%1,%2,%3}, {%4,%5,%6,%7}, {%8,%9}, {%0,%1,%2,%3};\n"
        : "+f"(c[0]), "+f"(c[1]), "+f"(c[2]), "+f"(c[3])
        : "r"(a[0]), "r"(a[1]), "r"(a[2]), "r"(a[3]), "r"(b0), "r"(b1));
}

__device__ __forceinline__ unsigned packh2(float lo, float hi) {
    unsigned r;
    asm("cvt.rn.f16x2.f32 %0, %1, %2;" : "=r"(r) : "f"(hi), "f"(lo));
    return r;   // low 16 bits = lo, high = hi
}

#define LDSM4(r, addr) \
    asm volatile("ldmatrix.sync.aligned.m8n8.x4.shared.b16 {%0,%1,%2,%3}, [%4];" \
        : "=r"((r)[0]), "=r"((r)[1]), "=r"((r)[2]), "=r"((r)[3]) : "r"(addr))

#define CP16(dst, src) \
    asm volatile("cp.async.cg.shared.global [%0], [%1], 16;" :: "r"(dst), "l"(src))
#define CPCOMMIT() asm volatile("cp.async.commit_group;" ::: "memory")
#define CPWAIT0()  asm volatile("cp.async.wait_group 0;" ::: "memory")

// ---------------- kernel 1: preprocessing (roll + stable sort + features) ---
__global__ __launch_bounds__(256) void prep_kernel(
    const float* __restrict__ x, const float* __restrict__ memory,
    const void* __restrict__ timings_raw, const float* __restrict__ msurp,
    const float* __restrict__ lastpred) {
    int b = blockIdx.x, s = threadIdx.x;
    __shared__ int t_sh[M_];
    __shared__ int rank_sh[M_];
    __shared__ float red[256];
    __shared__ int hi_nonzero;

    if (s == 0) hi_nonzero = 0;
    __syncthreads();
    {   // dtype sniff: int64 -> high 32-bit words of first 256 entries all 0
        const unsigned* w32 = (const unsigned*)timings_raw;
        if (w32[2 * s + 1] != 0u) hi_nonzero = 1;
    }
    __syncthreads();
    int is64 = !hi_nonzero;

    int t;
    if (s == 0) {
        t = 0;
    } else {
        int src = b * M_ + s - 1;
        long long tv = is64 ? ((const long long*)timings_raw)[src]
                            : (long long)((const int*)timings_raw)[src];
        t = (int)tv + 1;
    }
    t_sh[s] = t;
    __syncthreads();

    int r = 0, mx = 0;
#pragma unroll 8
    for (int j = 0; j < M_; ++j) {
        int tj = t_sh[j];
        mx = max(mx, tj);
        r += (tj < t) || (tj == t && j < s);
    }
    rank_sh[s] = r;

    float pv = (s < V_) ? x[b * V_ + s] * lastpred[b * V_ + s] : 0.f;
    red[s] = pv;
    __syncthreads();
    for (int off = 128; off; off >>= 1) {
        if (s < off) red[s] += red[s + off];
        __syncthreads();
    }
    float surprise = -logf(red[0] + 1e-8f);

    float invd = 1.f / ((float)mx + 1.f);
    __half* base = g_predh + (size_t)b * IN_DIM;

#pragma unroll
    for (int d = 0; d < TD; ++d)
        base[M_ * V_ + r * TD + d] = __float2half_rn((float)((t >> d) & 1));
    base[M_ * V_ + M_ * TD + r] = __float2half_rn((float)t * invd);
    float sv = (s == 0) ? surprise : msurp[b * M_ + s - 1] * 0.99f;
    base[M_ * V_ + M_ * TD + M_ + r] = __float2half_rn(sv);

    for (int e = s; e < M_ * V_; e += 256) {
        int sl = e >> 7, v = e & (V_ - 1);
        float val = sl ? memory[((size_t)(b * M_ + sl - 1)) * V_ + v]
                       : x[b * V_ + v];
        base[rank_sh[sl] * V_ + v] = __float2half_rn(val);
    }
}

// ------- kernel 2: fused dual FP16 GEMM, BK=64, 2-stage cp.async, LDSM ------
__global__ __launch_bounds__(256, 2) void gemm_kernel(
    const float* __restrict__ W1, const float* __restrict__ Wg) {
    extern __shared__ char smem[];
    const int tid = threadIdx.x, lane = tid & 31, warp = tid >> 5;
    const int wm = warp >> 2, wn = warp & 3;  // 2x4 warp grid, warp tile 64x16
    const int g = lane >> 2, q = lane & 3;
    const int n0 = blockIdx.x * BN;
    const int bm0 = blockIdx.y * BM;
    const int z = blockIdx.z;
    const int k0 = z * KPC;

    const unsigned sb = (unsigned)__cvta_generic_to_shared(smem);

    // LDSM lane address (within A stage): mi = lane>>3 selects 8x8 matrix
    const int mi = lane >> 3;
    const int abase_lane = (wm * 64 + (mi & 1) * 8 + (lane & 7)) * PAB + (mi >> 1) * 16;

    // ---- load maps (imm-offset form, ~8 addressing regs) ----
    // A: thread -> (row = tid>>3 + i*32, col16 = tid&7), i = 0..3
    const __half* asrc = g_predh + (size_t)(bm0 + (tid >> 3)) * IN_DIM + k0 + (tid & 7) * 8;
    const unsigned adst = (unsigned)((tid >> 3) * PAB + (tid & 7) * 16);
    // B: thread -> (krow = tid>>4 + i*16, cc = tid&15) per mat, i = 0..3
    const float* b1src = W1 + (size_t)(k0 + (tid >> 4)) * H_ + n0 + (tid & 15) * 4;
    const float* bgsrc = Wg + (size_t)(k0 + (tid >> 4)) * H_ + n0 + (tid & 15) * 4;
    const unsigned bdst = (unsigned)(A_STG + (tid >> 4) * (PWF * 4) + (tid & 15) * 16);

    auto issue = [&](int s) {
        unsigned st = sb + (unsigned)((s & 1) * STG);
        const __half* as = asrc + (size_t)s * BK;
        const float* b1s = b1src + (size_t)s * BK * H_;
        const float* bgs = bgsrc + (size_t)s * BK * H_;
#pragma unroll
        for (int i = 0; i < 4; ++i)
            CP16(st + adst + i * (32 * PAB), as + (size_t)i * 32 * IN_DIM);
#pragma unroll
        for (int i = 0; i < 4; ++i)
            CP16(st + bdst + i * (16 * PWF * 4), b1s + (size_t)i * 16 * H_);
#pragma unroll
        for (int i = 0; i < 4; ++i)
            CP16(st + bdst + B_MAT + i * (16 * PWF * 4), bgs + (size_t)i * 16 * H_);
    };

    float acc1[4][2][4], accg[4][2][4];
#pragma unroll
    for (int mf = 0; mf < 4; ++mf)
#pragma unroll
        for (int nf = 0; nf < 2; ++nf)
#pragma unroll
            for (int i = 0; i < 4; ++i) { acc1[mf][nf][i] = 0.f; accg[mf][nf][i] = 0.f; }

    issue(0); CPCOMMIT();

    for (int kb = 0; kb < NITER; ++kb) {
        CPWAIT0();            // stage kb fully landed
        __syncthreads();      // all threads: data visible + prev slot drained
        if (kb + 1 < NITER) { issue(kb + 1); CPCOMMIT(); }

        const char* stg = smem + (kb & 1) * STG;
        const float* B1 = (const float*)(stg + A_STG);
        const float* Bg = (const float*)(stg + A_STG + B_MAT);
        const unsigned abase = sb + (unsigned)((kb & 1) * STG + abase_lane);

#pragma unroll
        for (int kk = 0; kk < 4; ++kk) {      // four k16 slabs of BK=64
            unsigned a[4][4];
#pragma unroll
            for (int mf = 0; mf < 4; ++mf)
                LDSM4(a[mf], abase + (unsigned)(mf * 16 * PAB + kk * 32));
            int kt = kk * 16;
            unsigned b1f[2][2], bgf[2][2];
#pragma unroll
            for (int nf = 0; nf < 2; ++nf) {
                int col = wn * 16 + nf * 8 + g;
                const float* p1 = B1 + (kt + 2 * q) * PWF + col;
                const float* pg = Bg + (kt + 2 * q) * PWF + col;
                b1f[nf][0] = packh2(p1[0],        p1[PWF]);
                b1f[nf][1] = packh2(p1[8 * PWF],  p1[9 * PWF]);
                bgf[nf][0] = packh2(pg[0],        pg[PWF]);
                bgf[nf][1] = packh2(pg[8 * PWF],  pg[9 * PWF]);
            }
#pragma unroll
            for (int mf = 0; mf < 4; ++mf)
#pragma unroll
                for (int nf = 0; nf < 2; ++nf) {
                    mma16(acc1[mf][nf], a[mf], b1f[nf][0], b1f[nf][1]);
                    mma16(accg[mf][nf], a[mf], bgf[nf][0], bgf[nf][1]);
                }
        }
    }

    // epilogue: deterministic per-chunk partial writes
    float* o1 = g_h1p[z];
    float* og = g_hgp[z];
#pragma unroll
    for (int mf = 0; mf < 4; ++mf) {
        int row = bm0 + wm * 64 + mf * 16 + g;
#pragma unroll
        for (int nf = 0; nf < 2; ++nf) {
            int col = n0 + wn * 16 + nf * 8 + 2 * q;
            *(float2*)&o1[(size_t)row * H_ + col]       = make_float2(acc1[mf][nf][0], acc1[mf][nf][1]);
            *(float2*)&o1[(size_t)(row + 8) * H_ + col] = make_float2(acc1[mf][nf][2], acc1[mf][nf][3]);
            *(float2*)&og[(size_t)row * H_ + col]       = make_float2(accg[mf][nf][0], accg[mf][nf][1]);
            *(float2*)&og[(size_t)(row + 8) * H_ + col] = make_float2(accg[mf][nf][2], accg[mf][nf][3]);
        }
    }
}

// ---- kernel 3: fused gate + h @ W2 partials (NB=4 b-rows per block) --------
__global__ __launch_bounds__(256) void out_part_kernel(
    const float* __restrict__ W2, const float* __restrict__ b1,
    const float* __restrict__ bg) {
    __shared__ float hs[NB][256];
    __shared__ float part[NB][8 * 132];
    int bg0 = blockIdx.x, kc = blockIdx.y, tid = threadIdx.x;
    int b0 = bg0 * NB;
    int j = kc * 256 + tid;                    // h index within H
    float bb1 = b1[j], bbg = bg[j];

#pragma unroll
    for (int nb = 0; nb < NB; ++nb) {
        int idx = (b0 + nb) * H_ + j;
        float s1 = 0.f, sg = 0.f;
#pragma unroll
        for (int c = 0; c < KC; ++c) { s1 += g_h1p[c][idx]; sg += g_hgp[c][idx]; }
        float pre = s1 + bb1;
        float gv = sg + bbg;
        hs[nb][tid] = pre * (1.f / (1.f + expf(-gv)));
    }
    __syncthreads();

    int c = tid >> 5, vl = tid & 31, v4 = vl * 4;
    const float* wb = W2 + (size_t)(kc * 256 + c * 32) * V_ + v4;
    float4 acc[NB];
#pragma unroll
    for (int nb = 0; nb < NB; ++nb) acc[nb] = make_float4(0.f, 0.f, 0.f, 0.f);
#pragma unroll 4
    for (int i = 0; i < 32; ++i) {
        float4 w = *(const float4*)(wb + (size_t)i * V_);
#pragma unroll
        for (int nb = 0; nb < NB; ++nb) {
            float h = hs[nb][c * 32 + i];
            acc[nb].x += h * w.x; acc[nb].y += h * w.y;
            acc[nb].z += h * w.z; acc[nb].w += h * w.w;
        }
    }
#pragma unroll
    for (int nb = 0; nb < NB; ++nb)
        *(float4*)&part[nb][c * 132 + v4] = acc[nb];
    __syncthreads();

    if (tid < V_) {
#pragma unroll
        for (int nb = 0; nb < NB; ++nb) {
            float s = 0.f;
#pragma unroll
            for (int cc = 0; cc < 8; ++cc) s += part[nb][cc * 132 + tid];
            g_opart[kc][(b0 + nb) * V_ + tid] = s;
        }
    }
}

// -------- kernel 4: reduce out partials + bias ------------------------------
__global__ __launch_bounds__(256) void out_reduce_kernel(
    const float* __restrict__ b2, float* __restrict__ out) {
    int idx = blockIdx.x * 256 + threadIdx.x;    // B*V = 32768
    float s = b2[idx & (V_ - 1)];
#pragma unroll
    for (int kc = 0; kc < 4; ++kc) s += g_opart[kc][idx];
    out[idx] = s;
}

// ---------------- launch ----------------------------------------------------
extern "C" void kernel_launch(void* const* d_in, const int* in_sizes, int n_in,
                              void* d_out, int out_size) {
    const float* x        = (const float*)d_in[0];
    const float* memory   = (const float*)d_in[1];
    const void*  timings  = d_in[2];   // int32 or int64, sniffed on device
    const float* msurp    = (const float*)d_in[3];
    const float* lastpred = (const float*)d_in[4];
    const float* W1       = (const float*)d_in[5];
    const float* b1       = (const float*)d_in[6];
    const float* Wg       = (const float*)d_in[7];
    const float* bg       = (const float*)d_in[8];
    const float* W2       = (const float*)d_in[9];
    const float* b2       = (const float*)d_in[10];
    float* out = (float*)d_out;

    cudaFuncSetAttribute(gemm_kernel, cudaFuncAttributeMaxDynamicSharedMemorySize,
                         SMEM_BYTES);

    prep_kernel<<<B_, 256>>>(x, memory, timings, msurp, lastpred);
    gemm_kernel<<<dim3(H_ / BN, B_ / BM, KC), 256, SMEM_BYTES>>>(W1, Wg);
    out_part_kernel<<<dim3(B_ / NB, 4), 256>>>(W2, b1, bg);
    out_reduce_kernel<<<(B_ * V_) / 256, 256>>>(b2, out);
}

// round 17
// speedup vs baseline: 1.2639x; 1.2639x over previous
#include <cuda_runtime.h>
#include <cuda_fp16.h>
#include <math.h>

#define B_ 256
#define V_ 128
#define M_ 256
#define H_ 1024
#define TD 10
#define IN_DIM 35840          // (V + TD + 1 + 1) * M
#define KC 8                  // split-K chunks
#define KPC (IN_DIM / KC)     // 4480
#define BM 128
#define BN 64                 // per weight matrix (dual-gemm per CTA)
#define BK 32
#define NITER (KPC / BK)      // 140
#define PAB 80                // A smem row pitch in BYTES (32 halves + 16B pad)
#define PWB 68                // B smem row pitch in floats (272 B)
#define A_STG_BYTES (BM * PAB)                 // 10240
#define B_STG_BYTES (BK * PWB * 4)             // 8704 per mat
#define STG_BYTES (A_STG_BYTES + 2 * B_STG_BYTES)   // 27648
#define SMEM_BYTES (3 * STG_BYTES)             // 82944 -> 2 CTAs/SM
#define NB 2                  // b-rows per out block

// ---------------- device scratch (no allocations allowed) ----------------
__device__ __half g_predh[B_ * IN_DIM];     // fp16-rounded features
__device__ float g_h1p[KC][B_ * H_];        // split-K partials, GEMM 1
__device__ float g_hgp[KC][B_ * H_];        // split-K partials, gate GEMM

__device__ __forceinline__ void mma16(float c[4], const unsigned a[4],
                                      unsigned b0, unsigned b1) {
    asm volatile(
        "mma.sync.aligned.m16n8k16.row.col.f32.f16.f16.f32 "
        "{%0,%1,%2,%3}, {%4,%5,%6,%7}, {%8,%9}, {%0,%1,%2,%3};\n"
        : "+f"(c[0]), "+f"(c[1]), "+f"(c[2]), "+f"(c[3])
        : "r"(a[0]), "r"(a[1]), "r"(a[2]), "r"(a[3]), "r"(b0), "r"(b1));
}

__device__ __forceinline__ unsigned packh2(float lo, float hi) {
    unsigned r;
    asm("cvt.rn.f16x2.f32 %0, %1, %2;" : "=r"(r) : "f"(hi), "f"(lo));
    return r;   // low 16 bits = lo, high = hi
}

#define LDSM4(r, addr) \
    asm volatile("ldmatrix.sync.aligned.m8n8.x4.shared.b16 {%0,%1,%2,%3}, [%4];" \
        : "=r"((r)[0]), "=r"((r)[1]), "=r"((r)[2]), "=r"((r)[3]) : "r"(addr))

#define CP16(dst, src) \
    asm volatile("cp.async.cg.shared.global [%0], [%1], 16;" :: "r"(dst), "l"(src))
#define CPCOMMIT() asm volatile("cp.async.commit_group;" ::: "memory")
#define CPWAIT1()  asm volatile("cp.async.wait_group 1;" ::: "memory")

// ---------------- kernel 1: preprocessing (roll + stable sort + features) ---
__global__ __launch_bounds__(256) void prep_kernel(
    const float* __restrict__ x, const float* __restrict__ memory,
    const void* __restrict__ timings_raw, const float* __restrict__ msurp,
    const float* __restrict__ lastpred) {
    int b = blockIdx.x, s = threadIdx.x;
    __shared__ int t_sh[M_];
    __shared__ int rank_sh[M_];
    __shared__ float red[256];
    __shared__ int hi_nonzero;

    if (s == 0) hi_nonzero = 0;
    __syncthreads();
    {   // dtype sniff: int64 -> high 32-bit words of first 256 entries all 0
        const unsigned* w32 = (const unsigned*)timings_raw;
        if (w32[2 * s + 1] != 0u) hi_nonzero = 1;
    }
    __syncthreads();
    int is64 = !hi_nonzero;

    int t;
    if (s == 0) {
        t = 0;
    } else {
        int src = b * M_ + s - 1;
        long long tv = is64 ? ((const long long*)timings_raw)[src]
                            : (long long)((const int*)timings_raw)[src];
        t = (int)tv + 1;
    }
    t_sh[s] = t;
    __syncthreads();

    int r = 0, mx = 0;
#pragma unroll 8
    for (int j = 0; j < M_; ++j) {
        int tj = t_sh[j];
        mx = max(mx, tj);
        r += (tj < t) || (tj == t && j < s);
    }
    rank_sh[s] = r;

    float pv = (s < V_) ? x[b * V_ + s] * lastpred[b * V_ + s] : 0.f;
    red[s] = pv;
    __syncthreads();
    for (int off = 128; off; off >>= 1) {
        if (s < off) red[s] += red[s + off];
        __syncthreads();
    }
    float surprise = -logf(red[0] + 1e-8f);

    float invd = 1.f / ((float)mx + 1.f);
    __half* base = g_predh + (size_t)b * IN_DIM;

#pragma unroll
    for (int d = 0; d < TD; ++d)
        base[M_ * V_ + r * TD + d] = __float2half_rn((float)((t >> d) & 1));
    base[M_ * V_ + M_ * TD + r] = __float2half_rn((float)t * invd);
    float sv = (s == 0) ? surprise : msurp[b * M_ + s - 1] * 0.99f;
    base[M_ * V_ + M_ * TD + M_ + r] = __float2half_rn(sv);

    for (int e = s; e < M_ * V_; e += 256) {
        int sl = e >> 7, v = e & (V_ - 1);
        float val = sl ? memory[((size_t)(b * M_ + sl - 1)) * V_ + v]
                       : x[b * V_ + v];
        base[rank_sh[sl] * V_ + v] = __float2half_rn(val);
    }
}

// ------- kernel 2: fused dual FP16 GEMM (R13 verbatim — proven 221.2) -------
__global__ __launch_bounds__(256, 2) void gemm_kernel(
    const float* __restrict__ W1, const float* __restrict__ Wg) {
    extern __shared__ char smem[];
    const int tid = threadIdx.x, lane = tid & 31, warp = tid >> 5;
    const int wm = warp >> 2, wn = warp & 3;  // 2x4 warp grid, warp tile 64x16
    const int g = lane >> 2, q = lane & 3;
    const int n0 = blockIdx.x * BN;
    const int bm0 = blockIdx.y * BM;
    const int z = blockIdx.z;
    const int k0 = z * KPC;

    unsigned sb = (unsigned)__cvta_generic_to_shared(smem);

    const int mi = lane >> 3;
    const int abase_lane = (wm * 64 + (mi & 1) * 8 + (lane & 7)) * PAB + (mi >> 1) * 16;

    const __half* asrc[2]; unsigned adst[2];
    const float* bsrc[4];  unsigned bdst[4];
#pragma unroll
    for (int i = 0; i < 2; ++i) {
        int c = tid + i * 256;                   // 0..511
        int row = c >> 2, col4 = c & 3;          // 128 rows x 4 chunks (64B/row)
        asrc[i] = g_predh + (size_t)(bm0 + row) * IN_DIM + k0 + col4 * 8;
        adst[i] = (unsigned)(row * PAB + col4 * 16);
    }
#pragma unroll
    for (int i = 0; i < 4; ++i) {
        int c = tid + i * 256;                   // 0..1023
        int mat = c >> 9, rr = c & 511;
        int krow = rr >> 4, cc = rr & 15;        // 32 rows x 16 chunks (256B/row)
        bsrc[i] = (mat ? Wg : W1) + (size_t)(k0 + krow) * H_ + n0 + cc * 4;
        bdst[i] = (unsigned)(A_STG_BYTES + mat * B_STG_BYTES + krow * (PWB * 4) + cc * 16);
    }

    auto issue = [&](int s) {
        unsigned st = sb + (unsigned)((s % 3) * STG_BYTES);
        int kg = s * BK;
#pragma unroll
        for (int i = 0; i < 2; ++i)
            CP16(st + adst[i], asrc[i] + kg);
#pragma unroll
        for (int i = 0; i < 4; ++i)
            CP16(st + bdst[i], bsrc[i] + (size_t)kg * H_);
    };

    float acc1[4][2][4], accg[4][2][4];
#pragma unroll
    for (int mf = 0; mf < 4; ++mf)
#pragma unroll
        for (int nf = 0; nf < 2; ++nf)
#pragma unroll
            for (int i = 0; i < 4; ++i) { acc1[mf][nf][i] = 0.f; accg[mf][nf][i] = 0.f; }

    issue(0); CPCOMMIT();
    issue(1); CPCOMMIT();

    for (int kb = 0; kb < NITER; ++kb) {
        CPWAIT1();            // stage kb landed (one stage still in flight)
        __syncthreads();      // prev-iter reads of slot (kb+2)%3 done
        if (kb + 2 < NITER) issue(kb + 2);
        CPCOMMIT();           // empty group at tail keeps wait math valid

        const char* stg = smem + (kb % 3) * STG_BYTES;
        const float* B1 = (const float*)(stg + A_STG_BYTES);
        const float* Bg = (const float*)(stg + A_STG_BYTES + B_STG_BYTES);
        const unsigned abase = sb + (unsigned)((kb % 3) * STG_BYTES + abase_lane);

#pragma unroll
        for (int kk = 0; kk < 2; ++kk) {      // two k16 slabs of BK=32
            unsigned a[4][4];
#pragma unroll
            for (int mf = 0; mf < 4; ++mf)
                LDSM4(a[mf], abase + (unsigned)(mf * 16 * PAB + kk * 32));
            int kt = kk * 16;
            unsigned b1f[2][2], bgf[2][2];
#pragma unroll
            for (int nf = 0; nf < 2; ++nf) {
                int col = wn * 16 + nf * 8 + g;
                const float* p1 = B1 + (kt + 2 * q) * PWB + col;
                const float* pg = Bg + (kt + 2 * q) * PWB + col;
                b1f[nf][0] = packh2(p1[0],        p1[PWB]);
                b1f[nf][1] = packh2(p1[8 * PWB],  p1[9 * PWB]);
                bgf[nf][0] = packh2(pg[0],        pg[PWB]);
                bgf[nf][1] = packh2(pg[8 * PWB],  pg[9 * PWB]);
            }
#pragma unroll
            for (int mf = 0; mf < 4; ++mf)
#pragma unroll
                for (int nf = 0; nf < 2; ++nf) {
                    mma16(acc1[mf][nf], a[mf], b1f[nf][0], b1f[nf][1]);
                    mma16(accg[mf][nf], a[mf], bgf[nf][0], bgf[nf][1]);
                }
        }
    }

    // epilogue: deterministic per-chunk partial writes
    float* o1 = g_h1p[z];
    float* og = g_hgp[z];
#pragma unroll
    for (int mf = 0; mf < 4; ++mf) {
        int row = bm0 + wm * 64 + mf * 16 + g;
#pragma unroll
        for (int nf = 0; nf < 2; ++nf) {
            int col = n0 + wn * 16 + nf * 8 + 2 * q;
            *(float2*)&o1[(size_t)row * H_ + col]       = make_float2(acc1[mf][nf][0], acc1[mf][nf][1]);
            *(float2*)&o1[(size_t)(row + 8) * H_ + col] = make_float2(acc1[mf][nf][2], acc1[mf][nf][3]);
            *(float2*)&og[(size_t)row * H_ + col]       = make_float2(accg[mf][nf][0], accg[mf][nf][1]);
            *(float2*)&og[(size_t)(row + 8) * H_ + col] = make_float2(accg[mf][nf][2], accg[mf][nf][3]);
        }
    }
}

// ---- kernel 3: fused gate + h @ W2 + b2, kc-folded, direct output ----------
// NB=2 b-rows/block, grid 128 (~1 wave). W2 traffic 64 MB (L2-resident-ish).
__global__ __launch_bounds__(256) void out_kernel(
    const float* __restrict__ W2, const float* __restrict__ b1,
    const float* __restrict__ bg, const float* __restrict__ b2,
    float* __restrict__ out) {
    __shared__ float hs[NB][256];
    __shared__ float part[NB][8 * 132];
    const int b0 = blockIdx.x * NB, tid = threadIdx.x;
    const int c = tid >> 5, vl = tid & 31, v4 = vl * 4;

    float4 acc[NB];
#pragma unroll
    for (int nb = 0; nb < NB; ++nb) acc[nb] = make_float4(0.f, 0.f, 0.f, 0.f);

    for (int kc = 0; kc < 4; ++kc) {
        int j = kc * 256 + tid;
        float bb1 = b1[j], bbg = bg[j];
        __syncthreads();        // hs reuse guard (prior kc reads finished)
#pragma unroll
        for (int nb = 0; nb < NB; ++nb) {
            int idx = (b0 + nb) * H_ + j;
            float s1 = 0.f, sg = 0.f;
#pragma unroll
            for (int cz = 0; cz < KC; ++cz) { s1 += g_h1p[cz][idx]; sg += g_hgp[cz][idx]; }
            float pre = s1 + bb1;
            float gv = sg + bbg;
            hs[nb][tid] = pre * (1.f / (1.f + expf(-gv)));
        }
        __syncthreads();

        const float* wb = W2 + (size_t)(kc * 256 + c * 32) * V_ + v4;
#pragma unroll 4
        for (int i = 0; i < 32; ++i) {
            float4 w = *(const float4*)(wb + (size_t)i * V_);
#pragma unroll
            for (int nb = 0; nb < NB; ++nb) {
                float h = hs[nb][c * 32 + i];
                acc[nb].x += h * w.x; acc[nb].y += h * w.y;
                acc[nb].z += h * w.z; acc[nb].w += h * w.w;
            }
        }
    }

#pragma unroll
    for (int nb = 0; nb < NB; ++nb)
        *(float4*)&part[nb][c * 132 + v4] = acc[nb];
    __syncthreads();

    if (tid < V_) {
#pragma unroll
        for (int nb = 0; nb < NB; ++nb) {
            float s = b2[tid];
#pragma unroll
            for (int cc = 0; cc < 8; ++cc) s += part[nb][cc * 132 + tid];
            out[(b0 + nb) * V_ + tid] = s;
        }
    }
}

// ---------------- launch ----------------------------------------------------
extern "C" void kernel_launch(void* const* d_in, const int* in_sizes, int n_in,
                              void* d_out, int out_size) {
    const float* x        = (const float*)d_in[0];
    const float* memory   = (const float*)d_in[1];
    const void*  timings  = d_in[2];   // int32 or int64, sniffed on device
    const float* msurp    = (const float*)d_in[3];
    const float* lastpred = (const float*)d_in[4];
    const float* W1       = (const float*)d_in[5];
    const float* b1       = (const float*)d_in[6];
    const float* Wg       = (const float*)d_in[7];
    const float* bg       = (const float*)d_in[8];
    const float* W2       = (const float*)d_in[9];
    const float* b2       = (const float*)d_in[10];
    float* out = (float*)d_out;

    cudaFuncSetAttribute(gemm_kernel, cudaFuncAttributeMaxDynamicSharedMemorySize,
                         SMEM_BYTES);

    prep_kernel<<<B_, 256>>>(x, memory, timings, msurp, lastpred);
    gemm_kernel<<<dim3(H_ / BN, B_ / BM, KC), 256, SMEM_BYTES>>>(W1, Wg);
    out_kernel<<<B_ / NB, 256>>>(W2, b1, bg, b2, out);
}